// round 11
// baseline (speedup 1.0000x reference)
#include <cuda_runtime.h>
#include <cuda_fp16.h>
#include <cstdint>

#define MAXN 50000
#define MAXE 800000

// ================= device scratch =================
struct __align__(8) Edge8 { int row; __half2 c; };   // c = (dis[row], c2)

__device__ __half g_xcat[MAXN * 256];
__device__ __half g_xpeh[MAXN * 256];
__device__ __half g_xmh [MAXN * 128];
__device__ __half g_wb  [256 * 256];
__device__ __half g_ws  [4][128 * 256];
__device__ int   g_cnt [2 * MAXN];
__device__ int   g_off0[MAXN + 1];
__device__ int   g_off1[MAXN + 1];
__device__ int   g_cur0[MAXN];
__device__ int   g_cur1[MAXN];
__device__ float g_dis0[MAXN];
__device__ float g_dis1[MAXN];
__device__ Edge8 g_ent0[MAXE];
__device__ Edge8 g_ent1[MAXE];

// ================= batched graph preprocessing =================
__global__ void k_count2(const int* __restrict__ c0, const int* __restrict__ c1,
                         int* __restrict__ cnt0, int* __restrict__ cnt1, int e) {
    int i = blockIdx.x * blockDim.x + threadIdx.x;
    const int* col = blockIdx.y ? c1 : c0;
    int* cnt = blockIdx.y ? cnt1 : cnt0;
    if (i < e) atomicAdd(&cnt[col[i]], 1);
}
__global__ void k_scan2(const int* __restrict__ cnt0, const int* __restrict__ cnt1,
                        int* __restrict__ off0, int* __restrict__ off1,
                        int* __restrict__ cur0, int* __restrict__ cur1,
                        float* __restrict__ dis0, float* __restrict__ dis1, int n) {
    __shared__ int s[1024];
    const int* cnt = blockIdx.x ? cnt1 : cnt0;
    int* off = blockIdx.x ? off1 : off0;
    int* cur = blockIdx.x ? cur1 : cur0;
    float* dis = blockIdx.x ? dis1 : dis0;
    int t = threadIdx.x;
    int chunk = (n + 1023) >> 10;
    int b = t * chunk;
    int e = min(b + chunk, n);
    int sum = 0;
    for (int i = b; i < e; i++) sum += cnt[i];
    s[t] = sum;
    __syncthreads();
    for (int o = 1; o < 1024; o <<= 1) {
        int v = (t >= o) ? s[t - o] : 0;
        __syncthreads();
        s[t] += v;
        __syncthreads();
    }
    int base = s[t] - sum;
    for (int i = b; i < e; i++) {
        int c = cnt[i];
        off[i] = base; cur[i] = base; base += c;
        dis[i] = rsqrtf((float)(c + 1));
    }
    if (t == 1023) off[n] = s[1023];
}
__global__ void k_fill2(const int* __restrict__ ei0, const float* __restrict__ ea0,
                        const int* __restrict__ ei1, const float* __restrict__ ea1,
                        const float* __restrict__ dis0, const float* __restrict__ dis1,
                        int* __restrict__ cur0, int* __restrict__ cur1,
                        Edge8* __restrict__ ent0, Edge8* __restrict__ ent1, int e) {
    int i = blockIdx.x * blockDim.x + threadIdx.x;
    if (i >= e) return;
    const int* ei = blockIdx.y ? ei1 : ei0;
    const float* attr = blockIdx.y ? ea1 : ea0;
    const float* dis = blockIdx.y ? dis1 : dis0;
    int* cur = blockIdx.y ? cur1 : cur0;
    Edge8* ent = blockIdx.y ? ent1 : ent0;
    int r = ei[i], c = ei[e + i];
    float a = attr[i];
    float c2 = (a > 0.f) ? fminf(rsqrtf(a), 1.f) : 0.f;
    Edge8 rec;
    rec.row = r;
    rec.c = __floats2half2_rn(dis[r], c2);
    int p = atomicAdd(&cur[c], 1);
    ent[p] = rec;
}

// ================= fused xcat (fp16) + wtcat prep ======================
__global__ void k_xcatwt(const float* __restrict__ x, const float* __restrict__ pe,
                         const float* __restrict__ w1, const float* __restrict__ w2,
                         __half* __restrict__ xc, __half* __restrict__ wb,
                         int n, int nxblk) {
    int b = blockIdx.x;
    int t = threadIdx.x;
    if (b >= nxblk) {
        int idx = (b - nxblk) * 256 + t;
        int nn = idx >> 8, k = idx & 255;
        float v = 0.f;
        if (k < 226) v = (nn < 128) ? w1[k * 128 + nn] : w2[k * 128 + (nn - 128)];
        wb[idx] = __float2half_rn(v);
        return;
    }
    int row = b * 4 + (t >> 6);
    if (row >= n) return;
    int k = (t & 63) * 4;
    float v0, v1, v2, v3;
    if (k < 128) {
        float4 xv = *reinterpret_cast<const float4*>(x + (size_t)row * 128 + k);
        v0 = xv.x; v1 = xv.y; v2 = xv.z; v3 = xv.w;
    } else {
        int pk = k - 128;
        const float* pr = pe + (size_t)row * 98;
        if (pk + 1 < 98) { float2 p = *reinterpret_cast<const float2*>(pr + pk); v0 = p.x; v1 = p.y; }
        else             { v0 = 0.f; v1 = 0.f; }
        if (pk + 3 < 98) { float2 p = *reinterpret_cast<const float2*>(pr + pk + 2); v2 = p.x; v3 = p.y; }
        else             { v2 = 0.f; v3 = 0.f; }
    }
    size_t o = (size_t)row * 256 + k;
    __half2* hp = reinterpret_cast<__half2*>(xc + o);
    hp[0] = __floats2half2_rn(v0, v1);
    hp[1] = __floats2half2_rn(v2, v3);
}

__global__ void k_wtstk4(const float* __restrict__ w10, const float* __restrict__ w20,
                         const float* __restrict__ w11, const float* __restrict__ w21,
                         const float* __restrict__ w12, const float* __restrict__ w22,
                         const float* __restrict__ w13, const float* __restrict__ w23,
                         __half* __restrict__ w) {
    int idx = blockIdx.x * blockDim.x + threadIdx.x;
    if (idx >= 128 * 256) return;
    int g = blockIdx.y;
    const float* w1 = (g == 0) ? w10 : (g == 1) ? w11 : (g == 2) ? w12 : w13;
    const float* w2 = (g == 0) ? w20 : (g == 1) ? w21 : (g == 2) ? w22 : w23;
    int n = idx >> 8, k = idx & 255;
    float v = (k < 128) ? w1[k * 128 + n] : w2[(k - 128) * 128 + n];
    w[g * 32768 + idx] = __float2half_rn(v);
}

// ================= common PTX helpers =========================
__device__ __forceinline__ uint32_t smem_u32(const void* p) {
    uint32_t a;
    asm("{ .reg .u64 t; cvta.to.shared.u64 t, %1; cvt.u32.u64 %0, t; }" : "=r"(a) : "l"(p));
    return a;
}
__device__ __forceinline__ void cp16(uint32_t dst, const void* src) {
    asm volatile("cp.async.cg.shared.global [%0], [%1], 16;" :: "r"(dst), "l"(src));
}
__device__ __forceinline__ void cp_commit() { asm volatile("cp.async.commit_group;"); }
template <int W> __device__ __forceinline__ void cp_wait() {
    asm volatile("cp.async.wait_group %0;" :: "n"(W));
}
__device__ __forceinline__ void ldm_x4(uint32_t* r, uint32_t addr) {
    asm volatile("ldmatrix.sync.aligned.m8n8.x4.shared.b16 {%0,%1,%2,%3}, [%4];"
                 : "=r"(r[0]), "=r"(r[1]), "=r"(r[2]), "=r"(r[3]) : "r"(addr));
}
__device__ __forceinline__ void mma16816(float* c, const uint32_t* a, uint32_t b0, uint32_t b1) {
    asm volatile(
        "mma.sync.aligned.m16n8k16.row.col.f32.f16.f16.f32 "
        "{%0,%1,%2,%3}, {%4,%5,%6,%7}, {%8,%9}, {%0,%1,%2,%3};"
        : "+f"(c[0]), "+f"(c[1]), "+f"(c[2]), "+f"(c[3])
        : "r"(a[0]), "r"(a[1]), "r"(a[2]), "r"(a[3]), "r"(b0), "r"(b1));
}
__device__ __forceinline__ float4 ld_half4(const __half* p) {
    uint2 raw = *reinterpret_cast<const uint2*>(p);
    __half2 h0 = *reinterpret_cast<const __half2*>(&raw.x);
    __half2 h1 = *reinterpret_cast<const __half2*>(&raw.y);
    float2 f0 = __half22float2(h0), f1 = __half22float2(h1);
    return make_float4(f0.x, f0.y, f1.x, f1.y);
}

// ================= stage B: HMMA fp16 GEMM (xcat @ Wcat) ==============
struct GArgs {
    const __half* A;         // [M,256]
    const __half* B;         // [256,256] transposed weights
    __half* C;
    int M;
};

__global__ void __launch_bounds__(256, 2) k_gemmB(GArgs args) {
    constexpr int APL  = 16384;              // 128 rows x 128B per kc chunk
    constexpr int BPL  = 128 * 128;          // NT=128 rows x 128B
    constexpr int BUF  = APL + BPL;

    extern __shared__ char sm[];
    const int tid  = threadIdx.x;
    const int lane = tid & 31;
    const int wid  = tid >> 5;
    const int wm   = wid & 3;
    const int wn   = wid >> 2;
    const int m0   = blockIdx.y * 128;
    const int n0   = blockIdx.x * 128;
    const uint32_t sbase = smem_u32(sm);

    const int lr = tid >> 3, lq = tid & 7;

    auto issue_load = [&](int kc, int buf) {
        uint32_t sb = sbase + buf * BUF;
#pragma unroll
        for (int j = 0; j < 4; j++) {
            int r = lr + j * 32;
            int gr = m0 + r; if (gr > args.M - 1) gr = args.M - 1;
            cp16(sb + r * 128 + ((lq ^ (r & 7)) << 4),
                 args.A + (size_t)gr * 256 + kc * 64 + lq * 8);
        }
#pragma unroll
        for (int j = 0; j < 4; j++) {
            int r = lr + j * 32;
            cp16(sb + APL + r * 128 + ((lq ^ (r & 7)) << 4),
                 args.B + (size_t)(n0 + r) * 256 + kc * 64 + lq * 8);
        }
        cp_commit();
    };

    float acc[2][8][4];
#pragma unroll
    for (int mi = 0; mi < 2; mi++)
#pragma unroll
        for (int ni = 0; ni < 8; ni++)
#pragma unroll
            for (int k = 0; k < 4; k++) acc[mi][ni][k] = 0.f;

    issue_load(0, 0);
    for (int kc = 0; kc < 4; kc++) {
        if (kc < 3) { issue_load(kc + 1, (kc + 1) & 1); cp_wait<1>(); }
        else        { cp_wait<0>(); }
        __syncthreads();
        uint32_t sb = sbase + (kc & 1) * BUF;
#pragma unroll
        for (int ks = 0; ks < 4; ks++) {
            uint32_t af[2][4];
#pragma unroll
            for (int mi = 0; mi < 2; mi++) {
                int row = wm * 32 + mi * 16 + (lane & 15);
                int c16 = (2 * ks + (lane >> 4)) ^ (row & 7);
                ldm_x4(af[mi], sb + row * 128 + (c16 << 4));
            }
            uint32_t bf[8][2];
#pragma unroll
            for (int np = 0; np < 4; np++) {
                int nrow = wn * 64 + np * 16 + ((lane >> 4) << 3) + (lane & 7);
                int c16 = (2 * ks + ((lane >> 3) & 1)) ^ (nrow & 7);
                uint32_t t4[4];
                ldm_x4(t4, sb + APL + nrow * 128 + (c16 << 4));
                bf[np * 2][0] = t4[0]; bf[np * 2][1] = t4[1];
                bf[np * 2 + 1][0] = t4[2]; bf[np * 2 + 1][1] = t4[3];
            }
#pragma unroll
            for (int mi = 0; mi < 2; mi++)
#pragma unroll
                for (int ni = 0; ni < 8; ni++)
                    mma16816(acc[mi][ni], af[mi], bf[ni][0], bf[ni][1]);
        }
        __syncthreads();
    }

#pragma unroll
    for (int mi = 0; mi < 2; mi++) {
#pragma unroll
        for (int half = 0; half < 2; half++) {
            int r = m0 + wm * 32 + mi * 16 + (lane >> 2) + half * 8;
            if (r >= args.M) continue;
            size_t cbase = (size_t)r * 256 + n0 + wn * 64 + (lane & 3) * 2;
#pragma unroll
            for (int ni = 0; ni < 8; ni++) {
                __half2 hv = __floats2half2_rn(acc[mi][ni][half * 2],
                                               acc[mi][ni][half * 2 + 1]);
                *reinterpret_cast<__half2*>(args.C + cbase + ni * 8) = hv;
            }
        }
    }
}

// ================= FUSED gather + dual-source GEMM ====================
// CTA: 64-node m-tile. Phase 1: warps CSR-gather both graphs' aggregates
// into swizzled A smem [2 src][64 rows][256 cols fp16]. Phase 2: dual-source
// HMMA mainloop, B single-buffered per kc chunk.
// C = 0.5*relu(A0 @ B0^T) + 0.5*relu(A1 @ B1^T), NC = 128.
#define FA_SRC 32768                 // bytes per A source (64*256*2)
#define FB_OFF 65536                 // B buffer offset
#define FB_SRC 16384                 // bytes per B source per kc (128*128)
#define SMEM_FUSED (65536 + 32768)   // 98304

template <bool OUTH>
__global__ void __launch_bounds__(256, 2) k_fused(
    const __half* __restrict__ src, int ld, int coff1,
    const int* __restrict__ offs0, const int* __restrict__ offs1,
    const Edge8* __restrict__ ent0, const Edge8* __restrict__ ent1,
    const float* __restrict__ dis0, const float* __restrict__ dis1,
    const __half* __restrict__ B0, const __half* __restrict__ B1,
    void* __restrict__ C, int n) {
    extern __shared__ char sm[];
    const int tid  = threadIdx.x;
    const int lane = tid & 31;
    const int wid  = tid >> 5;
    const int m0   = blockIdx.x * 64;
    const uint32_t sbase = smem_u32(sm);

    const int lr = tid >> 3, lq = tid & 7;

    auto issue_B = [&](int kc) {
        const __half* Bs[2] = { B0, B1 };
#pragma unroll
        for (int s = 0; s < 2; s++) {
            uint32_t sb = sbase + FB_OFF + s * FB_SRC;
#pragma unroll
            for (int j = 0; j < 2; j++) {
                int r = lr + j * 32;       // 64 rows... need 128: lr in 0..31, j<4
                cp16(sb + r * 128 + ((lq ^ (r & 7)) << 4),
                     Bs[s] + (size_t)r * 256 + kc * 64 + lq * 8);
                int r2 = r + 64;
                cp16(sb + r2 * 128 + ((lq ^ (r2 & 7)) << 4),
                     Bs[s] + (size_t)r2 * 256 + kc * 64 + lq * 8);
            }
        }
        cp_commit();
    };

    // prefetch B chunk 0 before gather
    issue_B(0);

    // ---- Phase 1: gather into A smem ----
    // lane covers cols [4*lane, 4*lane+4) of the 128-wide feature slice.
    // a1 -> tile cols 4l..4l+3 ; a2 -> tile cols 128+4l..+3
    auto a_off = [&](int g, int r, int c) -> int {
        return g * FA_SRC + ((c >> 6) << 13) + r * 128
             + (((((c >> 3) & 7) ^ (r & 7))) << 4) + ((c & 7) << 1);
    };
    auto st8 = [&](int off, float4 v) {
        __half2 h01 = __floats2half2_rn(v.x, v.y);
        __half2 h23 = __floats2half2_rn(v.z, v.w);
        uint2 val;
        val.x = *reinterpret_cast<uint32_t*>(&h01);
        val.y = *reinterpret_cast<uint32_t*>(&h23);
        *reinterpret_cast<uint2*>(sm + off) = val;
    };

    for (int it = 0; it < 8; it++) {
        int r = it * 8 + wid;
        int node = m0 + r;
#pragma unroll
        for (int g = 0; g < 2; g++) {
            const int* offs = g ? offs1 : offs0;
            const Edge8* ent = g ? ent1 : ent0;
            const float* dis = g ? dis1 : dis0;
            int off = g ? coff1 : 0;
            float4 a1 = make_float4(0.f, 0.f, 0.f, 0.f);
            float4 a2 = make_float4(0.f, 0.f, 0.f, 0.f);
            if (node < n) {
                float d = dis[node];
                int b = offs[node], e = offs[node + 1];
                int i = b;
                for (; i + 4 <= e; i += 4) {
                    Edge8 rc[4];
#pragma unroll
                    for (int j = 0; j < 4; j++) rc[j] = ent[i + j];
                    float4 v[4];
#pragma unroll
                    for (int j = 0; j < 4; j++)
                        v[j] = ld_half4(src + (size_t)rc[j].row * ld + off + lane * 4);
#pragma unroll
                    for (int j = 0; j < 4; j++) {
                        float c1 = __low2float(rc[j].c) * d, c2 = __high2float(rc[j].c);
                        a1.x += c1 * v[j].x; a1.y += c1 * v[j].y; a1.z += c1 * v[j].z; a1.w += c1 * v[j].w;
                        a2.x += c2 * v[j].x; a2.y += c2 * v[j].y; a2.z += c2 * v[j].z; a2.w += c2 * v[j].w;
                    }
                }
                for (; i < e; i++) {
                    Edge8 rc = ent[i];
                    const float4 v = ld_half4(src + (size_t)rc.row * ld + off + lane * 4);
                    float c1 = __low2float(rc.c) * d, c2 = __high2float(rc.c);
                    a1.x += c1 * v.x; a1.y += c1 * v.y; a1.z += c1 * v.z; a1.w += c1 * v.w;
                    a2.x += c2 * v.x; a2.y += c2 * v.y; a2.z += c2 * v.z; a2.w += c2 * v.w;
                }
                float sc = d * d;
                const float4 v = ld_half4(src + (size_t)node * ld + off + lane * 4);
                a1.x += sc * v.x; a1.y += sc * v.y; a1.z += sc * v.z; a1.w += sc * v.w;
                a2.x += v.x;      a2.y += v.y;      a2.z += v.z;      a2.w += v.w;
            }
            st8(a_off(g, r, lane * 4), a1);
            st8(a_off(g, r, 128 + lane * 4), a2);
        }
    }

    cp_wait<0>();
    __syncthreads();

    // ---- Phase 2: dual-source GEMM from resident A ----
    const int wm = wid & 1;        // 2 m-warps x 32 rows
    const int wn = wid >> 1;       // 4 n-warps x 32 cols
    float acc[2][2][4][4];
#pragma unroll
    for (int s = 0; s < 2; s++)
#pragma unroll
        for (int mi = 0; mi < 2; mi++)
#pragma unroll
            for (int ni = 0; ni < 4; ni++)
#pragma unroll
                for (int k = 0; k < 4; k++) acc[s][mi][ni][k] = 0.f;

    for (int kc = 0; kc < 4; kc++) {
#pragma unroll
        for (int ks = 0; ks < 4; ks++) {
#pragma unroll
            for (int s = 0; s < 2; s++) {
                uint32_t af[2][4];
#pragma unroll
                for (int mi = 0; mi < 2; mi++) {
                    int row = wm * 32 + mi * 16 + (lane & 15);
                    int c16 = (2 * ks + (lane >> 4)) ^ (row & 7);
                    ldm_x4(af[mi], sbase + s * FA_SRC + (kc << 13) + row * 128 + (c16 << 4));
                }
                uint32_t bf[4][2];
#pragma unroll
                for (int np = 0; np < 2; np++) {
                    int nrow = wn * 32 + np * 16 + ((lane >> 4) << 3) + (lane & 7);
                    int c16 = (2 * ks + ((lane >> 3) & 1)) ^ (nrow & 7);
                    uint32_t t4[4];
                    ldm_x4(t4, sbase + FB_OFF + s * FB_SRC + nrow * 128 + (c16 << 4));
                    bf[np * 2][0] = t4[0]; bf[np * 2][1] = t4[1];
                    bf[np * 2 + 1][0] = t4[2]; bf[np * 2 + 1][1] = t4[3];
                }
#pragma unroll
                for (int mi = 0; mi < 2; mi++)
#pragma unroll
                    for (int ni = 0; ni < 4; ni++)
                        mma16816(acc[s][mi][ni], af[mi], bf[ni][0], bf[ni][1]);
            }
        }
        __syncthreads();           // all warps done reading B chunk
        if (kc < 3) {
            issue_B(kc + 1);
            cp_wait<0>();
            __syncthreads();
        }
    }

    // ---- epilogue ----
#pragma unroll
    for (int mi = 0; mi < 2; mi++) {
#pragma unroll
        for (int half = 0; half < 2; half++) {
            int r = m0 + wm * 32 + mi * 16 + (lane >> 2) + half * 8;
            if (r >= n) continue;
            size_t cbase = (size_t)r * 128 + wn * 32 + (lane & 3) * 2;
#pragma unroll
            for (int ni = 0; ni < 4; ni++) {
                float v0 = 0.5f * (fmaxf(acc[0][mi][ni][half * 2], 0.f) +
                                   fmaxf(acc[1][mi][ni][half * 2], 0.f));
                float v1 = 0.5f * (fmaxf(acc[0][mi][ni][half * 2 + 1], 0.f) +
                                   fmaxf(acc[1][mi][ni][half * 2 + 1], 0.f));
                if (OUTH) {
                    __half2 hv = __floats2half2_rn(v0, v1);
                    *reinterpret_cast<__half2*>((__half*)C + cbase + ni * 8) = hv;
                } else {
                    float* cp = (float*)C + cbase + ni * 8;
                    cp[0] = v0; cp[1] = v1;
                }
            }
        }
    }
}

#define SMEM_B1 (2 * (16384 + 128 * 128))              // 65536, double-buffered

// ================= host orchestration =================
extern "C" void kernel_launch(void* const* d_in, const int* in_sizes, int n_in,
                              void* d_out, int out_size) {
    const float* x   = (const float*)d_in[0];
    const float* pe  = (const float*)d_in[1];
    const int*   ei0 = (const int*)d_in[2];
    const float* ea0 = (const float*)d_in[3];
    const int*   ei1 = (const int*)d_in[4];
    const float* ea1 = (const float*)d_in[5];
    const float* nl1 = (const float*)d_in[6];
    const float* nl2 = (const float*)d_in[7];
    const float* lw[8] = { (const float*)d_in[8],  (const float*)d_in[9],
                           (const float*)d_in[10], (const float*)d_in[11],
                           (const float*)d_in[12], (const float*)d_in[13],
                           (const float*)d_in[14], (const float*)d_in[15] };
    float* out = (float*)d_out;

    int N = in_sizes[0] / 128;
    int E = in_sizes[3];

    __half *xc, *xpeh, *xmh, *wb, *ws;
    float *dis0, *dis1;
    int *cnt, *off0, *off1, *cur0, *cur1;
    Edge8 *ent0, *ent1;
    cudaGetSymbolAddress((void**)&xc,  g_xcat);
    cudaGetSymbolAddress((void**)&xpeh, g_xpeh);
    cudaGetSymbolAddress((void**)&xmh, g_xmh);
    cudaGetSymbolAddress((void**)&wb,  g_wb);
    cudaGetSymbolAddress((void**)&ws,  g_ws);
    cudaGetSymbolAddress((void**)&cnt, g_cnt);
    cudaGetSymbolAddress((void**)&off0, g_off0);
    cudaGetSymbolAddress((void**)&off1, g_off1);
    cudaGetSymbolAddress((void**)&cur0, g_cur0);
    cudaGetSymbolAddress((void**)&cur1, g_cur1);
    cudaGetSymbolAddress((void**)&dis0, g_dis0);
    cudaGetSymbolAddress((void**)&dis1, g_dis1);
    cudaGetSymbolAddress((void**)&ent0, g_ent0);
    cudaGetSymbolAddress((void**)&ent1, g_ent1);
    int* cnt0 = cnt;
    int* cnt1 = cnt + MAXN;

    cudaFuncSetAttribute((const void*)k_gemmB,
                         cudaFuncAttributeMaxDynamicSharedMemorySize, SMEM_B1);
    cudaFuncSetAttribute((const void*)k_fused<true>,
                         cudaFuncAttributeMaxDynamicSharedMemorySize, SMEM_FUSED);
    cudaFuncSetAttribute((const void*)k_fused<false>,
                         cudaFuncAttributeMaxDynamicSharedMemorySize, SMEM_FUSED);

    static cudaStream_t s1 = nullptr;
    static cudaEvent_t ev[2];
    if (s1 == nullptr) {
        cudaStreamCreateWithFlags(&s1, cudaStreamNonBlocking);
        for (int i = 0; i < 2; i++) cudaEventCreateWithFlags(&ev[i], cudaEventDisableTiming);
    }

    int eb = (E + 255) / 256;
    int mtiles = (N + 127) / 128;
    int ftiles = (N + 63) / 64;
    int nxblk = (N + 3) / 4;

    // ======== fork: preprocessing on s1 ========
    cudaEventRecord(ev[0], 0);
    cudaStreamWaitEvent(s1, ev[0], 0);

    cudaMemsetAsync(cnt, 0, 2 * MAXN * sizeof(int), s1);
    k_count2<<<dim3(eb, 2), 256, 0, s1>>>(ei0 + E, ei1 + E, cnt0, cnt1, E);
    k_scan2<<<2, 1024, 0, s1>>>(cnt0, cnt1, off0, off1, cur0, cur1, dis0, dis1, N);
    k_fill2<<<dim3(eb, 2), 256, 0, s1>>>(ei0, ea0, ei1, ea1, dis0, dis1,
                                         cur0, cur1, ent0, ent1, E);
    cudaEventRecord(ev[1], s1);

    // main: fused feature+wcat prep, stage B GEMM
    k_xcatwt<<<nxblk + 256, 256>>>(x, pe, nl1, nl2, xc, wb, N, nxblk);
    {
        GArgs a = { xc, wb, xpeh, N };
        k_gemmB<<<dim3(2, mtiles), 256, SMEM_B1>>>(a);
    }
    k_wtstk4<<<dim3(128, 4), 256>>>(lw[0], lw[1], lw[2], lw[3],
                                    lw[4], lw[5], lw[6], lw[7], ws);
    cudaStreamWaitEvent(0, ev[1], 0);   // join preprocessing

    // ======== fused stage C+D: gather(xpe) + GEMM -> xm (fp16) ========
    k_fused<true><<<ftiles, 256, SMEM_FUSED>>>(
        xpeh, 256, 128, off0, off1, ent0, ent1, dis0, dis1,
        ws + 0 * 32768, ws + 1 * 32768, xmh, N);

    // ======== fused stage E+F: gather(xm) + GEMM -> out (fp32) ========
    k_fused<false><<<ftiles, 256, SMEM_FUSED>>>(
        xmh, 128, 0, off0, off1, ent0, ent1, dis0, dis1,
        ws + 2 * 32768, ws + 3 * 32768, out, N);
}

// round 12
// speedup vs baseline: 1.3106x; 1.3106x over previous
#include <cuda_runtime.h>
#include <cuda_fp16.h>
#include <cstdint>

#define MAXN 50000
#define MAXE 800000

// ================= device scratch =================
struct __align__(8) Edge8 { int row; __half2 c; };   // c = (dis[row], c2)

__device__ __half g_xpeh[MAXN * 256];
__device__ __half g_a0  [MAXN * 256];
__device__ __half g_a1  [MAXN * 256];
__device__ __half g_xmh [MAXN * 128];
__device__ __half g_wb  [256 * 256];
__device__ __half g_ws  [4][128 * 256];
__device__ int   g_cnt [2 * MAXN];
__device__ int   g_off0[MAXN + 1];
__device__ int   g_off1[MAXN + 1];
__device__ int   g_cur0[MAXN];
__device__ int   g_cur1[MAXN];
__device__ float g_dis0[MAXN];
__device__ float g_dis1[MAXN];
__device__ Edge8 g_ent0[MAXE];
__device__ Edge8 g_ent1[MAXE];

// ================= batched graph preprocessing =================
__global__ void k_count2(const int* __restrict__ c0, const int* __restrict__ c1,
                         int* __restrict__ cnt0, int* __restrict__ cnt1, int e) {
    int i = blockIdx.x * blockDim.x + threadIdx.x;
    const int* col = blockIdx.y ? c1 : c0;
    int* cnt = blockIdx.y ? cnt1 : cnt0;
    if (i < e) atomicAdd(&cnt[col[i]], 1);
}
__global__ void k_scan2(const int* __restrict__ cnt0, const int* __restrict__ cnt1,
                        int* __restrict__ off0, int* __restrict__ off1,
                        int* __restrict__ cur0, int* __restrict__ cur1,
                        float* __restrict__ dis0, float* __restrict__ dis1, int n) {
    __shared__ int s[1024];
    const int* cnt = blockIdx.x ? cnt1 : cnt0;
    int* off = blockIdx.x ? off1 : off0;
    int* cur = blockIdx.x ? cur1 : cur0;
    float* dis = blockIdx.x ? dis1 : dis0;
    int t = threadIdx.x;
    int chunk = (n + 1023) >> 10;
    int b = t * chunk;
    int e = min(b + chunk, n);
    int sum = 0;
    for (int i = b; i < e; i++) sum += cnt[i];
    s[t] = sum;
    __syncthreads();
    for (int o = 1; o < 1024; o <<= 1) {
        int v = (t >= o) ? s[t - o] : 0;
        __syncthreads();
        s[t] += v;
        __syncthreads();
    }
    int base = s[t] - sum;
    for (int i = b; i < e; i++) {
        int c = cnt[i];
        off[i] = base; cur[i] = base; base += c;
        dis[i] = rsqrtf((float)(c + 1));
    }
    if (t == 1023) off[n] = s[1023];
}
__global__ void k_fill2(const int* __restrict__ ei0, const float* __restrict__ ea0,
                        const int* __restrict__ ei1, const float* __restrict__ ea1,
                        const float* __restrict__ dis0, const float* __restrict__ dis1,
                        int* __restrict__ cur0, int* __restrict__ cur1,
                        Edge8* __restrict__ ent0, Edge8* __restrict__ ent1, int e) {
    int i = blockIdx.x * blockDim.x + threadIdx.x;
    if (i >= e) return;
    const int* ei = blockIdx.y ? ei1 : ei0;
    const float* attr = blockIdx.y ? ea1 : ea0;
    const float* dis = blockIdx.y ? dis1 : dis0;
    int* cur = blockIdx.y ? cur1 : cur0;
    Edge8* ent = blockIdx.y ? ent1 : ent0;
    int r = ei[i], c = ei[e + i];
    float a = attr[i];
    float c2 = (a > 0.f) ? fminf(rsqrtf(a), 1.f) : 0.f;
    Edge8 rec;
    rec.row = r;
    rec.c = __floats2half2_rn(dis[r], c2);
    int p = atomicAdd(&cur[c], 1);
    ent[p] = rec;
}

// ================= weight prep ======================
__global__ void k_wtcat(const float* __restrict__ w1, const float* __restrict__ w2,
                        __half* __restrict__ w) {
    int idx = blockIdx.x * blockDim.x + threadIdx.x;
    if (idx >= 256 * 256) return;
    int n = idx >> 8, k = idx & 255;
    float v = 0.f;
    if (k < 226) v = (n < 128) ? w1[k * 128 + n] : w2[k * 128 + (n - 128)];
    w[idx] = __float2half_rn(v);
}
__global__ void k_wtstk4(const float* __restrict__ w10, const float* __restrict__ w20,
                         const float* __restrict__ w11, const float* __restrict__ w21,
                         const float* __restrict__ w12, const float* __restrict__ w22,
                         const float* __restrict__ w13, const float* __restrict__ w23,
                         __half* __restrict__ w) {
    int idx = blockIdx.x * blockDim.x + threadIdx.x;
    if (idx >= 128 * 256) return;
    int g = blockIdx.y;
    const float* w1 = (g == 0) ? w10 : (g == 1) ? w11 : (g == 2) ? w12 : w13;
    const float* w2 = (g == 0) ? w20 : (g == 1) ? w21 : (g == 2) ? w22 : w23;
    int n = idx >> 8, k = idx & 255;
    float v = (k < 128) ? w1[k * 128 + n] : w2[(k - 128) * 128 + n];
    w[g * 32768 + idx] = __float2half_rn(v);
}

// ================= common PTX helpers =========================
__device__ __forceinline__ uint32_t smem_u32(const void* p) {
    uint32_t a;
    asm("{ .reg .u64 t; cvta.to.shared.u64 t, %1; cvt.u32.u64 %0, t; }" : "=r"(a) : "l"(p));
    return a;
}
__device__ __forceinline__ void cp16(uint32_t dst, const void* src) {
    asm volatile("cp.async.cg.shared.global [%0], [%1], 16;" :: "r"(dst), "l"(src));
}
__device__ __forceinline__ void cp_commit() { asm volatile("cp.async.commit_group;"); }
template <int W> __device__ __forceinline__ void cp_wait() {
    asm volatile("cp.async.wait_group %0;" :: "n"(W));
}
__device__ __forceinline__ void ldm_x4(uint32_t* r, uint32_t addr) {
    asm volatile("ldmatrix.sync.aligned.m8n8.x4.shared.b16 {%0,%1,%2,%3}, [%4];"
                 : "=r"(r[0]), "=r"(r[1]), "=r"(r[2]), "=r"(r[3]) : "r"(addr));
}
__device__ __forceinline__ void mma16816(float* c, const uint32_t* a, uint32_t b0, uint32_t b1) {
    asm volatile(
        "mma.sync.aligned.m16n8k16.row.col.f32.f16.f16.f32 "
        "{%0,%1,%2,%3}, {%4,%5,%6,%7}, {%8,%9}, {%0,%1,%2,%3};"
        : "+f"(c[0]), "+f"(c[1]), "+f"(c[2]), "+f"(c[3])
        : "r"(a[0]), "r"(a[1]), "r"(a[2]), "r"(a[3]), "r"(b0), "r"(b1));
}
__device__ __forceinline__ float4 ld_half4(const __half* p) {
    uint2 raw = *reinterpret_cast<const uint2*>(p);
    __half2 h0 = *reinterpret_cast<const __half2*>(&raw.x);
    __half2 h1 = *reinterpret_cast<const __half2*>(&raw.y);
    float2 f0 = __half22float2(h0), f1 = __half22float2(h1);
    return make_float4(f0.x, f0.y, f1.x, f1.y);
}

// ================= stage B: fused A-construct + HMMA GEMM ==============
// A tile (128x256 fp16) built in smem directly from fp32 x/pe (no xcat buffer).
// B streams from wb via double-buffered cp.async. C = xpe (fp16).
#define BF_A 65536
#define BF_B 16384
#define SMEM_BF (BF_A + 2 * BF_B)   // 98304

__global__ void __launch_bounds__(256, 2) k_gemmBF(
    const float* __restrict__ x, const float* __restrict__ pe,
    const __half* __restrict__ wb, __half* __restrict__ xpe, int M) {
    extern __shared__ char sm[];
    const int tid  = threadIdx.x;
    const int lane = tid & 31;
    const int wid  = tid >> 5;
    const int wm   = wid & 3;
    const int wn   = wid >> 2;
    const int m0   = blockIdx.y * 128;
    const int n0   = blockIdx.x * 128;
    const uint32_t sbase = smem_u32(sm);
    const int lr = tid >> 3, lq = tid & 7;

    auto issue_B = [&](int kc, int buf) {
        uint32_t sb = sbase + BF_A + buf * BF_B;
#pragma unroll
        for (int j = 0; j < 4; j++) {
            int r = lr + j * 32;
            cp16(sb + r * 128 + ((lq ^ (r & 7)) << 4),
                 wb + (size_t)(n0 + r) * 256 + kc * 64 + lq * 8);
        }
        cp_commit();
    };
    issue_B(0, 0);

    // ---- construct full A tile (4 chunks of 16KB, swizzled) ----
    {
        int r = tid >> 1;
        int gr = m0 + r; if (gr > M - 1) gr = M - 1;
        int qb = (tid & 1) * 16;
        const float* xr = x + (size_t)gr * 128;
        const float* pr = pe + (size_t)gr * 98;
#pragma unroll
        for (int q = 0; q < 16; q++) {
            int gq = qb + q;              // col group: cols gq*8 .. gq*8+7
            int c0 = gq * 8;
            float v[8];
            if (c0 < 128) {
                float4 a = *reinterpret_cast<const float4*>(xr + c0);
                float4 b = *reinterpret_cast<const float4*>(xr + c0 + 4);
                v[0] = a.x; v[1] = a.y; v[2] = a.z; v[3] = a.w;
                v[4] = b.x; v[5] = b.y; v[6] = b.z; v[7] = b.w;
            } else {
#pragma unroll
                for (int p = 0; p < 4; p++) {
                    int pk = c0 + 2 * p - 128;
                    if (pk + 1 < 98) {
                        float2 t = *reinterpret_cast<const float2*>(pr + pk);
                        v[2 * p] = t.x; v[2 * p + 1] = t.y;
                    } else { v[2 * p] = 0.f; v[2 * p + 1] = 0.f; }
                }
            }
            uint4 val;
            __half2 h0 = __floats2half2_rn(v[0], v[1]);
            __half2 h1 = __floats2half2_rn(v[2], v[3]);
            __half2 h2 = __floats2half2_rn(v[4], v[5]);
            __half2 h3 = __floats2half2_rn(v[6], v[7]);
            val.x = *reinterpret_cast<uint32_t*>(&h0);
            val.y = *reinterpret_cast<uint32_t*>(&h1);
            val.z = *reinterpret_cast<uint32_t*>(&h2);
            val.w = *reinterpret_cast<uint32_t*>(&h3);
            uint32_t off = ((uint32_t)(gq >> 3) << 14) + r * 128
                         + (((gq & 7) ^ (r & 7)) << 4);
            *reinterpret_cast<uint4*>(sm + off) = val;
        }
    }

    float acc[2][8][4];
#pragma unroll
    for (int mi = 0; mi < 2; mi++)
#pragma unroll
        for (int ni = 0; ni < 8; ni++)
#pragma unroll
            for (int k = 0; k < 4; k++) acc[mi][ni][k] = 0.f;

    for (int kc = 0; kc < 4; kc++) {
        if (kc < 3) { issue_B(kc + 1, (kc + 1) & 1); cp_wait<1>(); }
        else        { cp_wait<0>(); }
        __syncthreads();
        uint32_t sa = sbase + ((uint32_t)kc << 14);
        uint32_t sb = sbase + BF_A + (kc & 1) * BF_B;
#pragma unroll
        for (int ks = 0; ks < 4; ks++) {
            uint32_t af[2][4];
#pragma unroll
            for (int mi = 0; mi < 2; mi++) {
                int row = wm * 32 + mi * 16 + (lane & 15);
                int c16 = (2 * ks + (lane >> 4)) ^ (row & 7);
                ldm_x4(af[mi], sa + row * 128 + (c16 << 4));
            }
            uint32_t bf[8][2];
#pragma unroll
            for (int np = 0; np < 4; np++) {
                int nrow = wn * 64 + np * 16 + ((lane >> 4) << 3) + (lane & 7);
                int c16 = (2 * ks + ((lane >> 3) & 1)) ^ (nrow & 7);
                uint32_t t4[4];
                ldm_x4(t4, sb + nrow * 128 + (c16 << 4));
                bf[np * 2][0] = t4[0]; bf[np * 2][1] = t4[1];
                bf[np * 2 + 1][0] = t4[2]; bf[np * 2 + 1][1] = t4[3];
            }
#pragma unroll
            for (int mi = 0; mi < 2; mi++)
#pragma unroll
                for (int ni = 0; ni < 8; ni++)
                    mma16816(acc[mi][ni], af[mi], bf[ni][0], bf[ni][1]);
        }
        __syncthreads();
    }

#pragma unroll
    for (int mi = 0; mi < 2; mi++) {
#pragma unroll
        for (int half = 0; half < 2; half++) {
            int r = m0 + wm * 32 + mi * 16 + (lane >> 2) + half * 8;
            if (r >= M) continue;
            size_t cbase = (size_t)r * 256 + n0 + wn * 64 + (lane & 3) * 2;
#pragma unroll
            for (int ni = 0; ni < 8; ni++) {
                __half2 hv = __floats2half2_rn(acc[mi][ni][half * 2],
                                               acc[mi][ni][half * 2 + 1]);
                *reinterpret_cast<__half2*>(xpe + cbase + ni * 8) = hv;
            }
        }
    }
}

// ================= merged CSR gather (both graphs, fp16 out) ==============
__device__ __forceinline__ void st_half4(__half* p, float4 v) {
    __half2* hp = reinterpret_cast<__half2*>(p);
    hp[0] = __floats2half2_rn(v.x, v.y);
    hp[1] = __floats2half2_rn(v.z, v.w);
}

__global__ void k_gather2(const __half* __restrict__ src, int ld, int coff1,
                          const int* __restrict__ offs0, const int* __restrict__ offs1,
                          const Edge8* __restrict__ ent0, const Edge8* __restrict__ ent1,
                          const float* __restrict__ dis0, const float* __restrict__ dis1,
                          __half* __restrict__ o0, __half* __restrict__ o1, int n) {
    int g = blockIdx.y;
    const int* offs = g ? offs1 : offs0;
    const Edge8* ent = g ? ent1 : ent0;
    const float* dis = g ? dis1 : dis0;
    __half* oh = g ? o1 : o0;
    int off = g ? coff1 : 0;

    int warp = (blockIdx.x * blockDim.x + threadIdx.x) >> 5;
    int lane = threadIdx.x & 31;
    if (warp >= n) return;
    float d = dis[warp];
    int b = offs[warp], e = offs[warp + 1];
    float4 a1 = make_float4(0.f, 0.f, 0.f, 0.f);
    float4 a2 = make_float4(0.f, 0.f, 0.f, 0.f);
    int i = b;
    for (; i + 4 <= e; i += 4) {
        Edge8 r[4];
#pragma unroll
        for (int j = 0; j < 4; j++) r[j] = ent[i + j];
        float4 v[4];
#pragma unroll
        for (int j = 0; j < 4; j++)
            v[j] = ld_half4(src + (size_t)r[j].row * ld + off + lane * 4);
#pragma unroll
        for (int j = 0; j < 4; j++) {
            float c1 = __low2float(r[j].c) * d, c2 = __high2float(r[j].c);
            a1.x += c1 * v[j].x; a1.y += c1 * v[j].y; a1.z += c1 * v[j].z; a1.w += c1 * v[j].w;
            a2.x += c2 * v[j].x; a2.y += c2 * v[j].y; a2.z += c2 * v[j].z; a2.w += c2 * v[j].w;
        }
    }
    for (; i < e; i++) {
        Edge8 rec = ent[i];
        const float4 v = ld_half4(src + (size_t)rec.row * ld + off + lane * 4);
        float c1 = __low2float(rec.c) * d, c2 = __high2float(rec.c);
        a1.x += c1 * v.x; a1.y += c1 * v.y; a1.z += c1 * v.z; a1.w += c1 * v.w;
        a2.x += c2 * v.x; a2.y += c2 * v.y; a2.z += c2 * v.z; a2.w += c2 * v.w;
    }
    float sc = d * d;
    const float4 v = ld_half4(src + (size_t)warp * ld + off + lane * 4);
    a1.x += sc * v.x; a1.y += sc * v.y; a1.z += sc * v.z; a1.w += sc * v.w;
    a2.x += v.x;      a2.y += v.y;      a2.z += v.z;      a2.w += v.w;
    size_t base = (size_t)warp * 256 + lane * 4;
    st_half4(oh + base,       a1);
    st_half4(oh + base + 128, a2);
}

// ================= HMMA fp16 dual-source GEMM (stages D/F) ================
struct GArgs {
    const __half* A[2];      // [src], fp16, [M,256]
    const __half* B[2];      // [src], fp16, [128,256] transposed weights
    void* C;
    int M, NC;
};

template <bool OUTH>
__global__ void __launch_bounds__(256, 2) k_gemm2(GArgs args) {
    constexpr int APL  = 16384;
    constexpr int ABUF = 2 * APL;
    constexpr int BPL  = 64 * 128;
    constexpr int BBUF = 2 * BPL;
    constexpr int BUF  = ABUF + BBUF;

    extern __shared__ char sm[];
    const int tid  = threadIdx.x;
    const int lane = tid & 31;
    const int wid  = tid >> 5;
    const int wm   = wid & 3;
    const int wn   = wid >> 2;
    const int m0   = blockIdx.y * 128;
    const int n0   = blockIdx.x * 64;
    const uint32_t sbase = smem_u32(sm);

    const int lr = tid >> 3, lq = tid & 7;

    auto issue_load = [&](int kc, int buf) {
        uint32_t sb = sbase + buf * BUF;
#pragma unroll
        for (int s = 0; s < 2; s++) {
            const __half* A = args.A[s];
            uint32_t sa = sb + s * APL;
#pragma unroll
            for (int j = 0; j < 4; j++) {
                int r = lr + j * 32;
                int gr = m0 + r; if (gr > args.M - 1) gr = args.M - 1;
                cp16(sa + r * 128 + ((lq ^ (r & 7)) << 4),
                     A + (size_t)gr * 256 + kc * 64 + lq * 8);
            }
        }
#pragma unroll
        for (int s = 0; s < 2; s++) {
            const __half* B = args.B[s];
            uint32_t sbB = sb + ABUF + s * BPL;
#pragma unroll
            for (int j = 0; j < 2; j++) {
                int r = lr + j * 32;
                cp16(sbB + r * 128 + ((lq ^ (r & 7)) << 4),
                     B + (size_t)(n0 + r) * 256 + kc * 64 + lq * 8);
            }
        }
        cp_commit();
    };

    float acc[2][2][4][4];
#pragma unroll
    for (int s = 0; s < 2; s++)
#pragma unroll
        for (int mi = 0; mi < 2; mi++)
#pragma unroll
            for (int ni = 0; ni < 4; ni++)
#pragma unroll
                for (int k = 0; k < 4; k++) acc[s][mi][ni][k] = 0.f;

    issue_load(0, 0);
    for (int kc = 0; kc < 4; kc++) {
        if (kc < 3) { issue_load(kc + 1, (kc + 1) & 1); cp_wait<1>(); }
        else        { cp_wait<0>(); }
        __syncthreads();
        uint32_t sb = sbase + (kc & 1) * BUF;
#pragma unroll
        for (int ks = 0; ks < 4; ks++) {
#pragma unroll
            for (int s = 0; s < 2; s++) {
                uint32_t af[2][4];
#pragma unroll
                for (int mi = 0; mi < 2; mi++) {
                    int row = wm * 32 + mi * 16 + (lane & 15);
                    int c16 = (2 * ks + (lane >> 4)) ^ (row & 7);
                    ldm_x4(af[mi], sb + s * APL + row * 128 + (c16 << 4));
                }
                uint32_t bf[4][2];
#pragma unroll
                for (int np = 0; np < 2; np++) {
                    int nrow = wn * 32 + np * 16 + ((lane >> 4) << 3) + (lane & 7);
                    int c16 = (2 * ks + ((lane >> 3) & 1)) ^ (nrow & 7);
                    uint32_t t4[4];
                    ldm_x4(t4, sb + ABUF + s * BPL + nrow * 128 + (c16 << 4));
                    bf[np * 2][0] = t4[0]; bf[np * 2][1] = t4[1];
                    bf[np * 2 + 1][0] = t4[2]; bf[np * 2 + 1][1] = t4[3];
                }
#pragma unroll
                for (int mi = 0; mi < 2; mi++)
#pragma unroll
                    for (int ni = 0; ni < 4; ni++)
                        mma16816(acc[s][mi][ni], af[mi], bf[ni][0], bf[ni][1]);
            }
        }
        __syncthreads();
    }

#pragma unroll
    for (int mi = 0; mi < 2; mi++) {
#pragma unroll
        for (int half = 0; half < 2; half++) {
            int r = m0 + wm * 32 + mi * 16 + (lane >> 2) + half * 8;
            if (r >= args.M) continue;
            size_t cbase = (size_t)r * args.NC + n0 + wn * 32 + (lane & 3) * 2;
#pragma unroll
            for (int ni = 0; ni < 4; ni++) {
                float v0 = 0.5f * (fmaxf(acc[0][mi][ni][half * 2], 0.f) +
                                   fmaxf(acc[1][mi][ni][half * 2], 0.f));
                float v1 = 0.5f * (fmaxf(acc[0][mi][ni][half * 2 + 1], 0.f) +
                                   fmaxf(acc[1][mi][ni][half * 2 + 1], 0.f));
                if (OUTH) {
                    __half2 hv = __floats2half2_rn(v0, v1);
                    *reinterpret_cast<__half2*>((__half*)args.C + cbase + ni * 8) = hv;
                } else {
                    float* cp = (float*)args.C + cbase + ni * 8;
                    cp[0] = v0; cp[1] = v1;
                }
            }
        }
    }
}

#define SMEM_DF (2 * (2 * 16384 + 2 * 64 * 128))       // 98304

// ================= host orchestration =================
extern "C" void kernel_launch(void* const* d_in, const int* in_sizes, int n_in,
                              void* d_out, int out_size) {
    const float* x   = (const float*)d_in[0];
    const float* pe  = (const float*)d_in[1];
    const int*   ei0 = (const int*)d_in[2];
    const float* ea0 = (const float*)d_in[3];
    const int*   ei1 = (const int*)d_in[4];
    const float* ea1 = (const float*)d_in[5];
    const float* nl1 = (const float*)d_in[6];
    const float* nl2 = (const float*)d_in[7];
    const float* lw[8] = { (const float*)d_in[8],  (const float*)d_in[9],
                           (const float*)d_in[10], (const float*)d_in[11],
                           (const float*)d_in[12], (const float*)d_in[13],
                           (const float*)d_in[14], (const float*)d_in[15] };
    float* out = (float*)d_out;

    int N = in_sizes[0] / 128;
    int E = in_sizes[3];

    __half *xpeh, *a0, *a1, *xmh, *wb, *ws;
    float *dis0, *dis1;
    int *cnt, *off0, *off1, *cur0, *cur1;
    Edge8 *ent0, *ent1;
    cudaGetSymbolAddress((void**)&xpeh, g_xpeh);
    cudaGetSymbolAddress((void**)&a0,  g_a0);
    cudaGetSymbolAddress((void**)&a1,  g_a1);
    cudaGetSymbolAddress((void**)&xmh, g_xmh);
    cudaGetSymbolAddress((void**)&wb,  g_wb);
    cudaGetSymbolAddress((void**)&ws,  g_ws);
    cudaGetSymbolAddress((void**)&cnt, g_cnt);
    cudaGetSymbolAddress((void**)&off0, g_off0);
    cudaGetSymbolAddress((void**)&off1, g_off1);
    cudaGetSymbolAddress((void**)&cur0, g_cur0);
    cudaGetSymbolAddress((void**)&cur1, g_cur1);
    cudaGetSymbolAddress((void**)&dis0, g_dis0);
    cudaGetSymbolAddress((void**)&dis1, g_dis1);
    cudaGetSymbolAddress((void**)&ent0, g_ent0);
    cudaGetSymbolAddress((void**)&ent1, g_ent1);
    int* cnt0 = cnt;
    int* cnt1 = cnt + MAXN;

    cudaFuncSetAttribute((const void*)k_gemmBF,
                         cudaFuncAttributeMaxDynamicSharedMemorySize, SMEM_BF);
    cudaFuncSetAttribute((const void*)k_gemm2<true>,
                         cudaFuncAttributeMaxDynamicSharedMemorySize, SMEM_DF);
    cudaFuncSetAttribute((const void*)k_gemm2<false>,
                         cudaFuncAttributeMaxDynamicSharedMemorySize, SMEM_DF);

    static cudaStream_t s1 = nullptr;
    static cudaEvent_t ev[2];
    if (s1 == nullptr) {
        cudaStreamCreateWithFlags(&s1, cudaStreamNonBlocking);
        for (int i = 0; i < 2; i++) cudaEventCreateWithFlags(&ev[i], cudaEventDisableTiming);
    }

    int eb = (E + 255) / 256;
    int mtiles = (N + 127) / 128;
    int gw = (N + 7) / 8;

    // ======== fork: preprocessing + ws prep on s1 ========
    cudaEventRecord(ev[0], 0);
    cudaStreamWaitEvent(s1, ev[0], 0);

    cudaMemsetAsync(cnt, 0, 2 * MAXN * sizeof(int), s1);
    k_count2<<<dim3(eb, 2), 256, 0, s1>>>(ei0 + E, ei1 + E, cnt0, cnt1, E);
    k_scan2<<<2, 1024, 0, s1>>>(cnt0, cnt1, off0, off1, cur0, cur1, dis0, dis1, N);
    k_fill2<<<dim3(eb, 2), 256, 0, s1>>>(ei0, ea0, ei1, ea1, dis0, dis1,
                                         cur0, cur1, ent0, ent1, E);
    k_wtstk4<<<dim3(128, 4), 256, 0, s1>>>(lw[0], lw[1], lw[2], lw[3],
                                           lw[4], lw[5], lw[6], lw[7], ws);
    cudaEventRecord(ev[1], s1);

    // main: wcat prep + fused stage B (A constructed in-kernel)
    k_wtcat<<<256, 256>>>(nl1, nl2, wb);
    k_gemmBF<<<dim3(2, mtiles), 256, SMEM_BF>>>(x, pe, wb, xpeh, N);
    cudaStreamWaitEvent(0, ev[1], 0);   // join preprocessing + ws

    // ======== stage C: both graphs in one launch ========
    k_gather2<<<dim3(gw, 2), 256>>>(xpeh, 256, 128, off0, off1, ent0, ent1,
                                    dis0, dis1, a0, a1, N);

    // ======== stage D (fused dual-source GEMM, fp16 xm output) ========
    {
        GArgs a = {};
        a.A[0] = a0; a.A[1] = a1;
        a.B[0] = ws + 0 * 32768;
        a.B[1] = ws + 1 * 32768;
        a.C = xmh; a.M = N; a.NC = 128;
        k_gemm2<true><<<dim3(2, mtiles), 256, SMEM_DF>>>(a);
    }

    // ======== stage E ========
    k_gather2<<<dim3(gw, 2), 256>>>(xmh, 128, 0, off0, off1, ent0, ent1,
                                    dis0, dis1, a0, a1, N);

    // ======== stage F (fused dual-source GEMM, fp32 out) ========
    {
        GArgs a = {};
        a.A[0] = a0; a.A[1] = a1;
        a.B[0] = ws + 2 * 32768;
        a.B[1] = ws + 3 * 32768;
        a.C = out; a.M = N; a.NC = 128;
        k_gemm2<false><<<dim3(2, mtiles), 256, SMEM_DF>>>(a);
    }
}